// round 1
// baseline (speedup 1.0000x reference)
#include <cuda_runtime.h>
#include <cstdint>

// Problem constants (fixed by the dataset):
//   inputs: [B=128, T=4096] f32
//   W:      [S=64, K=543]   f32 (Ricker bank)
//   out:    [B, S, T] f32, "same" cross-correlation:
//     out[b,s,t] = sum_{k=0}^{K-1} x[b, t + k - K/2] * W[s, k]   (zero-padded)

#define B_DIM   128
#define T_DIM   4096
#define S_DIM   64
#define K_DIM   543
#define K_HALF  271

#define TT      128          // time tile per block
#define KC      64           // k chunk staged in smem
#define KPAD    576          // 9 * 64, zero-padded K
#define NCHUNK  9
#define XS      (TT + KPAD)  // 704 floats of x staged per block

// Zero-padded transposed bank: W_T[k][s], k in [0,576), s in [0,64)
__device__ float g_WT[KPAD * S_DIM];

__global__ void transpose_bank_kernel(const float* __restrict__ W) {
    int idx = blockIdx.x * blockDim.x + threadIdx.x;
    if (idx >= KPAD * S_DIM) return;
    int k = idx / S_DIM;
    int s = idx % S_DIM;
    g_WT[idx] = (k < K_DIM) ? W[s * K_DIM + k] : 0.0f;
}

__global__ __launch_bounds__(128, 4)
void ricker_cwt_kernel(const float* __restrict__ x, float* __restrict__ out) {
    __shared__ float xs[XS];
    __shared__ float ws[KC][S_DIM];   // [k'][s], rows 256B -> float4 aligned

    const int tid    = threadIdx.x;        // 0..127
    const int tile_t = blockIdx.x * TT;    // 0..4096-128
    const int b      = blockIdx.y;         // 0..127

    const float* xrow = x + (size_t)b * T_DIM;

    // Stage x window: xs[i] = x[b, tile_t + i - K_HALF], zero-padded.
    #pragma unroll
    for (int i = tid; i < XS; i += 128) {
        int g = tile_t + i - K_HALF;
        xs[i] = (g >= 0 && g < T_DIM) ? xrow[g] : 0.0f;
    }

    const int tb = tid & 15;         // time base: thread covers t = tb + 16*j
    const int s0 = (tid >> 4) << 3;  // scale base: s0 .. s0+7

    float acc[8][8];                 // [j (time)][si (scale)]
    #pragma unroll
    for (int j = 0; j < 8; ++j)
        #pragma unroll
        for (int si = 0; si < 8; ++si) acc[j][si] = 0.0f;

    for (int c = 0; c < NCHUNK; ++c) {
        __syncthreads();   // previous chunk's compute done (and xs ready at c=0)
        // Stage W chunk (coalesced from pre-transposed, zero-padded bank)
        const float* wsrc = g_WT + c * (KC * S_DIM);
        float* wdst = &ws[0][0];
        #pragma unroll
        for (int i = tid; i < KC * S_DIM; i += 128) wdst[i] = wsrc[i];
        __syncthreads();

        const int xbase = tb + c * KC;
        #pragma unroll 4
        for (int k = 0; k < KC; ++k) {
            const float4 wa = *reinterpret_cast<const float4*>(&ws[k][s0]);
            const float4 wb = *reinterpret_cast<const float4*>(&ws[k][s0 + 4]);
            const float w[8] = {wa.x, wa.y, wa.z, wa.w, wb.x, wb.y, wb.z, wb.w};
            #pragma unroll
            for (int j = 0; j < 8; ++j) {
                const float xv = xs[xbase + k + 16 * j];
                #pragma unroll
                for (int si = 0; si < 8; ++si)
                    acc[j][si] = fmaf(xv, w[si], acc[j][si]);
            }
        }
    }

    // Write out[b, s0+si, tile_t + tb + 16*j]
    #pragma unroll
    for (int si = 0; si < 8; ++si) {
        float* orow = out + ((size_t)(b * S_DIM + s0 + si) * T_DIM) + tile_t + tb;
        #pragma unroll
        for (int j = 0; j < 8; ++j) orow[16 * j] = acc[j][si];
    }
}

extern "C" void kernel_launch(void* const* d_in, const int* in_sizes, int n_in,
                              void* d_out, int out_size) {
    const float* x = (const float*)d_in[0];   // [128, 4096]
    const float* W = (const float*)d_in[1];   // [64, 543]
    float* out = (float*)d_out;               // [128, 64, 4096]

    (void)in_sizes; (void)n_in; (void)out_size;

    // 1) Transpose + zero-pad the bank into __device__ scratch (graph-capturable).
    transpose_bank_kernel<<<(KPAD * S_DIM + 255) / 256, 256>>>(W);

    // 2) Main convolution: grid = (T/TT, B), 128 threads/block.
    dim3 grid(T_DIM / TT, B_DIM);
    ricker_cwt_kernel<<<grid, 128>>>(x, out);
}